// round 6
// baseline (speedup 1.0000x reference)
#include <cuda_runtime.h>
#include <cuda_fp16.h>
#include <cstdint>
#include <cstddef>

#define N_ATOMS 262144
#define BATCH   4096
#define HIDDEN  256
#define SCALE   0.125f
#define LN_EPS  1e-5f
#define SM_EPS  1e-16f

#define NTILES  (N_ATOMS / 64)      // 4096 tiles of 64 rows
#define NCTAS   148
#define APITCH  264                 // halves; 528B row stride = 4 banks mod 32
#define BPITCH  264

// ---------------- scratch (device globals, no allocation) ----------------
__device__ float    g_A[HIDDEN * HIDDEN];   // A = Wq @ Wk^T
__device__ float    g_dvec[HIDDEN];
__device__ float    g_vq[HIDDEN];
__device__ float    g_cconst[1];
__device__ float    g_U[BATCH * HIDDEN];
__device__ float    g_c[BATCH];
__device__ float    g_e[N_ATOMS];
__device__ unsigned g_segmax[BATCH];
__device__ float    g_segsum[BATCH];
__device__ __half   g_WvT16[HIDDEN * HIDDEN]; // WvT16[n][k] = fp16(Wv[k][n])

// ---------------- K0: zero segment reducers ----------------
__global__ void k_init() {
    int i = blockIdx.x * blockDim.x + threadIdx.x;
    if (i < BATCH) { g_segmax[i] = 0u; g_segsum[i] = 0.f; }
}

// ---------------- K1: A = Wq @ Wk^T, vq, dvec, cconst ----------------
__global__ void k_pre(const float* __restrict__ Wq, const float* __restrict__ bq,
                      const float* __restrict__ Wk, const float* __restrict__ bk) {
    int t = threadIdx.x;
    if (blockIdx.x < 32) {
        __shared__ float wq[8][HIDDEN];
        int k0 = blockIdx.x * 8;
        #pragma unroll
        for (int e = 0; e < 8; e++) wq[e][t] = Wq[(k0 + e) * HIDDEN + t];
        __syncthreads();
        float acc[8];
        #pragma unroll
        for (int r = 0; r < 8; r++) acc[r] = 0.f;
        for (int j = 0; j < HIDDEN; j++) {
            float w = __ldg(&Wk[t * HIDDEN + j]);
            #pragma unroll
            for (int r = 0; r < 8; r++) acc[r] += wq[r][j] * w;
        }
        #pragma unroll
        for (int r = 0; r < 8; r++) g_A[(k0 + r) * HIDDEN + t] = acc[r];
    } else {
        __shared__ float bqs[HIDDEN], bks[HIDDEN];
        bqs[t] = bq[t]; bks[t] = bk[t];
        __syncthreads();
        float v = 0.f, d = 0.f;
        for (int j = 0; j < HIDDEN; j++) {
            v += __ldg(&Wq[t * HIDDEN + j]) * bks[j];
            d += __ldg(&Wk[t * HIDDEN + j]) * bqs[j];
        }
        g_vq[t] = v; g_dvec[t] = d;
        if (t == 0) {
            float c = 0.f;
            for (int j = 0; j < HIDDEN; j++) c += bqs[j] * bks[j];
            g_cconst[0] = c;
        }
    }
}

// ---------------- K2: U = protein @ A + d ; c = protein @ vq + cc ----------------
__global__ void k_u(const float* __restrict__ P) {
    __shared__ float ps[HIDDEN][16];
    __shared__ float vqs[HIDDEN];
    int t = threadIdx.x;
    int b0 = blockIdx.x * 16;
    #pragma unroll
    for (int e = 0; e < 16; e++) ps[t][e] = P[(b0 + e) * HIDDEN + t];
    vqs[t] = g_vq[t];
    __syncthreads();
    float acc[16];
    #pragma unroll
    for (int r = 0; r < 16; r++) acc[r] = 0.f;
    for (int k = 0; k < HIDDEN; k++) {
        float a = g_A[k * HIDDEN + t];
        const float4* p4 = (const float4*)ps[k];
        float4 x0 = p4[0], x1 = p4[1], x2 = p4[2], x3 = p4[3];
        acc[0]  += x0.x * a; acc[1]  += x0.y * a; acc[2]  += x0.z * a; acc[3]  += x0.w * a;
        acc[4]  += x1.x * a; acc[5]  += x1.y * a; acc[6]  += x1.z * a; acc[7]  += x1.w * a;
        acc[8]  += x2.x * a; acc[9]  += x2.y * a; acc[10] += x2.z * a; acc[11] += x2.w * a;
        acc[12] += x3.x * a; acc[13] += x3.y * a; acc[14] += x3.z * a; acc[15] += x3.w * a;
    }
    float dv = g_dvec[t];
    #pragma unroll
    for (int r = 0; r < 16; r++) g_U[(b0 + r) * HIDDEN + t] = acc[r] + dv;
    if (t < 16) {
        float s = 0.f;
        for (int k = 0; k < HIDDEN; k++) s += ps[k][t] * vqs[k];
        g_c[b0 + t] = s + g_cconst[0];
    }
}

// ---------------- K2b: transpose Wv -> g_WvT16 (n-major, fp16) ----------------
__global__ void k_t(const float* __restrict__ Wv) {
    __shared__ float ts[32][33];
    int x = threadIdx.x, y = threadIdx.y;           // 32 x 8
    int bx = blockIdx.x * 32, by = blockIdx.y * 32;
    #pragma unroll
    for (int j = 0; j < 32; j += 8) ts[y + j][x] = Wv[(by + y + j) * HIDDEN + bx + x];
    __syncthreads();
    #pragma unroll
    for (int j = 0; j < 32; j += 8)
        g_WvT16[(bx + y + j) * HIDDEN + by + x] = __float2half_rn(ts[x][y + j]);
}

// ---------------- K3: dots + segment max (warp handles 2 atoms) ----------------
__device__ __forceinline__ unsigned f_key(float f) {
    unsigned b = __float_as_uint(f);
    return (b & 0x80000000u) ? ~b : (b | 0x80000000u);
}
__device__ __forceinline__ float key_f(unsigned k) {
    return (k & 0x80000000u) ? __uint_as_float(k ^ 0x80000000u) : __uint_as_float(~k);
}

__global__ void k_dots(const float* __restrict__ drug, const int* __restrict__ bidx) {
    int warp = threadIdx.x >> 5, lane = threadIdx.x & 31;
    int i0 = (blockIdx.x * 8 + warp) * 2;
    int b0 = bidx[i0], b1 = bidx[i0 + 1];
    const float4* d0 = (const float4*)(drug + (size_t)i0 * HIDDEN);
    const float4* d1 = (const float4*)(drug + (size_t)(i0 + 1) * HIDDEN);
    const float4* u0 = (const float4*)(g_U + (size_t)b0 * HIDDEN);
    const float4* u1 = (const float4*)(g_U + (size_t)b1 * HIDDEN);
    float4 x0 = d0[lane * 2], x1 = d0[lane * 2 + 1];
    float4 x2 = d1[lane * 2], x3 = d1[lane * 2 + 1];
    float4 y0 = u0[lane * 2], y1 = u0[lane * 2 + 1];
    float4 y2 = u1[lane * 2], y3 = u1[lane * 2 + 1];
    float s0 = x0.x * y0.x + x0.y * y0.y + x0.z * y0.z + x0.w * y0.w
             + x1.x * y1.x + x1.y * y1.y + x1.z * y1.z + x1.w * y1.w;
    float s1 = x2.x * y2.x + x2.y * y2.y + x2.z * y2.z + x2.w * y2.w
             + x3.x * y3.x + x3.y * y3.y + x3.z * y3.z + x3.w * y3.w;
    #pragma unroll
    for (int off = 16; off > 0; off >>= 1) {
        s0 += __shfl_xor_sync(0xFFFFFFFFu, s0, off);
        s1 += __shfl_xor_sync(0xFFFFFFFFu, s1, off);
    }
    if (lane == 0) {
        float v0 = (s0 + g_c[b0]) * SCALE;
        float v1 = (s1 + g_c[b1]) * SCALE;
        g_e[i0]     = v0;
        g_e[i0 + 1] = v1;
        atomicMax(&g_segmax[b0], f_key(v0));
        atomicMax(&g_segmax[b1], f_key(v1));
    }
}

// ---------------- K4: e = exp(dots - m), segment sum ----------------
__global__ void k_exp(const int* __restrict__ bidx) {
    int i = blockIdx.x * blockDim.x + threadIdx.x;
    int b = bidx[i];
    float m = key_f(g_segmax[b]);
    float e = expf(g_e[i] - m);
    g_e[i] = e;
    atomicAdd(&g_segsum[b], e);
}

// ---------------- K5: persistent fp16-mma V-GEMM + attn*V + residual + LN ------
// grid = 148 persistent CTAs, 512 threads. B (WvT fp16 256x256) SMEM-resident.
// Each CTA loops over M=64 tiles: next tile's A prefetched to registers before
// the mma burst, converted+STS at top of next iter. Epilogue re-reads fp32
// residual from gmem (L2-hot) and does the fused LN.

struct alignas(16) Sm {
    __half b[256 * BPITCH];            // 135,168 B
    __half a2[2][64 * APITCH];         //  67,584 B
    float  attn[64];
    float  bvv[HIDDEN], gm[HIDDEN], bt[HIDDEN];
    float  rs[4][64], rq[4][64];
};

__device__ __forceinline__ void cp16(void* s, const void* g) {
    unsigned sa = (unsigned)__cvta_generic_to_shared(s);
    asm volatile("cp.async.cg.shared.global [%0], [%1], 16;" :: "r"(sa), "l"(g));
}
__device__ __forceinline__ void ldsm4(unsigned* r, unsigned addr) {
    asm volatile("ldmatrix.sync.aligned.m8n8.x4.shared.b16 {%0,%1,%2,%3}, [%4];"
        : "=r"(r[0]), "=r"(r[1]), "=r"(r[2]), "=r"(r[3]) : "r"(addr));
}
__device__ __forceinline__ void mma16(float* c, const unsigned* a, const unsigned* b) {
    asm volatile(
        "mma.sync.aligned.m16n8k16.row.col.f32.f16.f16.f32 "
        "{%0,%1,%2,%3},{%4,%5,%6,%7},{%8,%9},{%0,%1,%2,%3};"
        : "+f"(c[0]), "+f"(c[1]), "+f"(c[2]), "+f"(c[3])
        : "r"(a[0]), "r"(a[1]), "r"(a[2]), "r"(a[3]), "r"(b[0]), "r"(b[1]));
}

__global__ void __launch_bounds__(512, 1) k_main(
    const float* __restrict__ drug, const int* __restrict__ bidx,
    const float* __restrict__ bv, const float* __restrict__ gamma,
    const float* __restrict__ beta,
    float* __restrict__ out, float* __restrict__ attn_out)
{
    extern __shared__ char smem_raw[];
    Sm& sm = *(Sm*)smem_raw;
    int t = threadIdx.x;
    int w = t >> 5, lane = t & 31;
    int g = lane >> 2, tig = lane & 3;
    int wm = w >> 2, wn = w & 3;       // 4x4 warps: M16 x N64 each

    // ---- one-time: B resident + bv/gamma/beta
    #pragma unroll
    for (int e = 0; e < 16; e++) {
        int idx = e * 512 + t;          // 8192 chunks of 8 halves
        int n = idx >> 5, j = idx & 31;
        cp16(&sm.b[n * BPITCH + j * 8], g_WvT16 + n * HIDDEN + j * 8);
    }
    asm volatile("cp.async.commit_group;");
    if (t < 256) { sm.bvv[t] = bv[t]; sm.gm[t] = gamma[t]; sm.bt[t] = beta[t]; }

    // preload first tile's A into registers
    float4 rA[8];
    int tl = blockIdx.x;
    {
        int rb = tl * 64;
        #pragma unroll
        for (int e = 0; e < 8; e++) {
            int idx = e * 512 + t;
            int row = idx >> 6, c4 = idx & 63;
            rA[e] = __ldg((const float4*)(drug + (size_t)(rb + row) * HIDDEN + c4 * 4));
        }
    }
    asm volatile("cp.async.wait_group 0;" ::: "memory");

    unsigned bBase = (unsigned)__cvta_generic_to_shared(sm.b);
    unsigned aBase0 = (unsigned)__cvta_generic_to_shared(sm.a2[0]);
    unsigned bLaneRow = (unsigned)((wn * 64 + ((lane >> 4) << 3) + (lane & 7)) * BPITCH * 2);
    unsigned bLaneK   = (unsigned)((((lane >> 3) & 1) << 3) * 2);
    unsigned aLaneOff = (unsigned)((wm * 16 + (lane & 15)) * APITCH * 2 + ((lane >> 4) << 3) * 2);

    int buf = 0;
    for (; tl < NTILES; tl += NCTAS) {
        int rb = tl * 64;
        int nxt = tl + NCTAS;

        // ---- cvt current A -> smem, prefetch next tile into rA
        #pragma unroll
        for (int e = 0; e < 8; e++) {
            int idx = e * 512 + t;
            int row = idx >> 6, c4 = idx & 63;
            __half2 h0 = __float22half2_rn(make_float2(rA[e].x, rA[e].y));
            __half2 h1 = __float22half2_rn(make_float2(rA[e].z, rA[e].w));
            *(uint2*)&sm.a2[buf][row * APITCH + c4 * 4] =
                make_uint2(*(unsigned*)&h0, *(unsigned*)&h1);
            if (nxt < NTILES)
                rA[e] = __ldg((const float4*)(drug + (size_t)(nxt * 64 + row) * HIDDEN + c4 * 4));
        }
        if (t < 64) {
            int i = rb + t;
            int b = bidx[i];
            float a = g_e[i] / (g_segsum[b] + SM_EPS);
            sm.attn[t] = a;
            if (attn_out) attn_out[i] = a;
        }
        __syncthreads();

        // ---- mma burst: M64 x N256 x K256, B resident, no waits
        float acc[8][4];
        #pragma unroll
        for (int nt = 0; nt < 8; nt++)
            #pragma unroll
            for (int q = 0; q < 4; q++) acc[nt][q] = 0.f;

        unsigned aLane = aBase0 + (unsigned)(buf * 64 * APITCH * 2) + aLaneOff;
        #pragma unroll
        for (int k16 = 0; k16 < 16; k16++) {
            unsigned a[4];
            ldsm4(a, aLane + (unsigned)(k16 * 16 * 2));
            #pragma unroll
            for (int p = 0; p < 4; p++) {
                unsigned bq[4];
                ldsm4(bq, bBase + bLaneRow + (unsigned)(p * 16 * BPITCH * 2)
                          + (unsigned)(k16 * 16 * 2) + bLaneK);
                mma16(acc[2 * p],     a, &bq[0]);
                mma16(acc[2 * p + 1], a, &bq[2]);
            }
        }

        // ---- epilogue: v = attn*(acc+bv) + drug ; LN across 4 N-warps
        int lr0 = wm * 16 + g, lr1 = lr0 + 8;
        float a0 = sm.attn[lr0], a1 = sm.attn[lr1];
        const float* drow0 = drug + (size_t)(rb + lr0) * HIDDEN;
        const float* drow1 = drug + (size_t)(rb + lr1) * HIDDEN;
        float rsum0 = 0.f, rsq0 = 0.f, rsum1 = 0.f, rsq1 = 0.f;
        #pragma unroll
        for (int nt = 0; nt < 8; nt++) {
            int c0 = wn * 64 + nt * 8 + 2 * tig;
            float2 q0 = __ldg((const float2*)(drow0 + c0));
            float2 q1 = __ldg((const float2*)(drow1 + c0));
            float bv0 = sm.bvv[c0], bv1 = sm.bvv[c0 + 1];
            float v0 = fmaf(a0, acc[nt][0] + bv0, q0.x);
            float v1 = fmaf(a0, acc[nt][1] + bv1, q0.y);
            float v2 = fmaf(a1, acc[nt][2] + bv0, q1.x);
            float v3 = fmaf(a1, acc[nt][3] + bv1, q1.y);
            acc[nt][0] = v0; acc[nt][1] = v1; acc[nt][2] = v2; acc[nt][3] = v3;
            rsum0 += v0 + v1;  rsq0 += v0 * v0 + v1 * v1;
            rsum1 += v2 + v3;  rsq1 += v2 * v2 + v3 * v3;
        }
        #pragma unroll
        for (int off = 1; off <= 2; off <<= 1) {
            rsum0 += __shfl_xor_sync(0xFFFFFFFFu, rsum0, off);
            rsq0  += __shfl_xor_sync(0xFFFFFFFFu, rsq0, off);
            rsum1 += __shfl_xor_sync(0xFFFFFFFFu, rsum1, off);
            rsq1  += __shfl_xor_sync(0xFFFFFFFFu, rsq1, off);
        }
        if (tig == 0) {
            sm.rs[wn][lr0] = rsum0; sm.rq[wn][lr0] = rsq0;
            sm.rs[wn][lr1] = rsum1; sm.rq[wn][lr1] = rsq1;
        }
        __syncthreads();

        #pragma unroll
        for (int h = 0; h < 2; h++) {
            int lr = wm * 16 + h * 8 + g;
            float ts = sm.rs[0][lr] + sm.rs[1][lr] + sm.rs[2][lr] + sm.rs[3][lr];
            float tq = sm.rq[0][lr] + sm.rq[1][lr] + sm.rq[2][lr] + sm.rq[3][lr];
            float mu = ts * (1.f / HIDDEN);
            float var = tq * (1.f / HIDDEN) - mu * mu;
            float rstd = rsqrtf(var + LN_EPS);
            #pragma unroll
            for (int nt = 0; nt < 8; nt++) {
                int c0 = wn * 64 + nt * 8 + 2 * tig;
                float v0 = acc[nt][h * 2 + 0];
                float v1 = acc[nt][h * 2 + 1];
                float y0 = fmaf((v0 - mu) * rstd, sm.gm[c0],     sm.bt[c0]);
                float y1 = fmaf((v1 - mu) * rstd, sm.gm[c0 + 1], sm.bt[c0 + 1]);
                *(float2*)&out[(size_t)(rb + lr) * HIDDEN + c0] = make_float2(y0, y1);
            }
        }
        buf ^= 1;
    }
}

// ---------------- host ----------------
extern "C" void kernel_launch(void* const* d_in, const int* in_sizes, int n_in,
                              void* d_out, int out_size) {
    const float* drug  = (const float*)d_in[0];
    const float* prot  = (const float*)d_in[1];
    const int*   bidx  = (const int*)d_in[2];
    const float* Wq    = (const float*)d_in[3];
    const float* bq    = (const float*)d_in[4];
    const float* Wk    = (const float*)d_in[5];
    const float* bk    = (const float*)d_in[6];
    const float* Wv    = (const float*)d_in[7];
    const float* bv    = (const float*)d_in[8];
    const float* gamma = (const float*)d_in[9];
    const float* beta  = (const float*)d_in[10];

    float* out = (float*)d_out;
    float* attn_out = (out_size >= (int)((size_t)N_ATOMS * HIDDEN + N_ATOMS))
                        ? out + (size_t)N_ATOMS * HIDDEN : nullptr;

    cudaFuncSetAttribute(k_main, cudaFuncAttributeMaxDynamicSharedMemorySize,
                         (int)sizeof(Sm));

    k_init<<<BATCH / 256, 256>>>();
    k_pre <<<33, 256>>>(Wq, bq, Wk, bk);
    k_u   <<<BATCH / 16, 256>>>(prot);
    k_t   <<<dim3(8, 8), dim3(32, 8)>>>(Wv);
    k_dots<<<N_ATOMS / 16, 256>>>(drug, bidx);
    k_exp <<<N_ATOMS / 256, 256>>>(bidx);
    k_main<<<NCTAS, 512, sizeof(Sm)>>>(drug, bidx, bv, gamma, beta, out, attn_out);
}

// round 7
// speedup vs baseline: 1.1809x; 1.1809x over previous
#include <cuda_runtime.h>
#include <cuda_fp16.h>
#include <cstdint>
#include <cstddef>

#define N_ATOMS 262144
#define BATCH   4096
#define HIDDEN  256
#define SCALE   0.125f
#define LN_EPS  1e-5f
#define SM_EPS  1e-16f

#define NTILES  (N_ATOMS / 128)     // 2048 tiles of 128 rows
#define NCTAS   148
#define APITCH  264                 // halves; 528B row = 4 banks mod 32
#define BPITCH  72                  // halves; 144B row = 4 banks mod 32

// ---------------- scratch (device globals, no allocation) ----------------
__device__ float    g_A[HIDDEN * HIDDEN];   // A = Wq @ Wk^T
__device__ float    g_dvec[HIDDEN];
__device__ float    g_vq[HIDDEN];
__device__ float    g_cconst[1];
__device__ float    g_U[BATCH * HIDDEN];
__device__ float    g_c[BATCH];
__device__ float    g_e[N_ATOMS];
__device__ unsigned g_segmax[BATCH];
__device__ float    g_segsum[BATCH];
__device__ __half   g_WvT16[HIDDEN * HIDDEN];       // WvT16[n][k] = fp16(Wv[k][n])
__device__ __half   g_drug16[(size_t)N_ATOMS * HIDDEN]; // fp16 copy of drug (128MB)

// ---------------- K1: A = Wq @ Wk^T, vq, dvec, cconst, zero reducers --------
__global__ void k_pre(const float* __restrict__ Wq, const float* __restrict__ bq,
                      const float* __restrict__ Wk, const float* __restrict__ bk) {
    int t = threadIdx.x;
    if (blockIdx.x < 32) {
        __shared__ float wq[8][HIDDEN];
        int k0 = blockIdx.x * 8;
        #pragma unroll
        for (int e = 0; e < 8; e++) wq[e][t] = Wq[(k0 + e) * HIDDEN + t];
        __syncthreads();
        float acc[8];
        #pragma unroll
        for (int r = 0; r < 8; r++) acc[r] = 0.f;
        for (int j = 0; j < HIDDEN; j++) {
            float w = __ldg(&Wk[t * HIDDEN + j]);
            #pragma unroll
            for (int r = 0; r < 8; r++) acc[r] += wq[r][j] * w;
        }
        #pragma unroll
        for (int r = 0; r < 8; r++) g_A[(k0 + r) * HIDDEN + t] = acc[r];
    } else {
        // zero segment reducers
        for (int i = t; i < BATCH; i += 256) { g_segmax[i] = 0u; g_segsum[i] = 0.f; }
        __shared__ float bqs[HIDDEN], bks[HIDDEN];
        bqs[t] = bq[t]; bks[t] = bk[t];
        __syncthreads();
        float v = 0.f, d = 0.f;
        for (int j = 0; j < HIDDEN; j++) {
            v += __ldg(&Wq[t * HIDDEN + j]) * bks[j];
            d += __ldg(&Wk[t * HIDDEN + j]) * bqs[j];
        }
        g_vq[t] = v; g_dvec[t] = d;
        if (t == 0) {
            float c = 0.f;
            for (int j = 0; j < HIDDEN; j++) c += bqs[j] * bks[j];
            g_cconst[0] = c;
        }
    }
}

// ---------------- K2: U = protein @ A + d ; c = protein @ vq + cc ----------------
__global__ void k_u(const float* __restrict__ P) {
    __shared__ float ps[HIDDEN][16];
    __shared__ float vqs[HIDDEN];
    int t = threadIdx.x;
    int b0 = blockIdx.x * 16;
    #pragma unroll
    for (int e = 0; e < 16; e++) ps[t][e] = P[(b0 + e) * HIDDEN + t];
    vqs[t] = g_vq[t];
    __syncthreads();
    float acc[16];
    #pragma unroll
    for (int r = 0; r < 16; r++) acc[r] = 0.f;
    for (int k = 0; k < HIDDEN; k++) {
        float a = g_A[k * HIDDEN + t];
        const float4* p4 = (const float4*)ps[k];
        float4 x0 = p4[0], x1 = p4[1], x2 = p4[2], x3 = p4[3];
        acc[0]  += x0.x * a; acc[1]  += x0.y * a; acc[2]  += x0.z * a; acc[3]  += x0.w * a;
        acc[4]  += x1.x * a; acc[5]  += x1.y * a; acc[6]  += x1.z * a; acc[7]  += x1.w * a;
        acc[8]  += x2.x * a; acc[9]  += x2.y * a; acc[10] += x2.z * a; acc[11] += x2.w * a;
        acc[12] += x3.x * a; acc[13] += x3.y * a; acc[14] += x3.z * a; acc[15] += x3.w * a;
    }
    float dv = g_dvec[t];
    #pragma unroll
    for (int r = 0; r < 16; r++) g_U[(b0 + r) * HIDDEN + t] = acc[r] + dv;
    if (t < 16) {
        float s = 0.f;
        for (int k = 0; k < HIDDEN; k++) s += ps[k][t] * vqs[k];
        g_c[b0 + t] = s + g_cconst[0];
    }
}

// ---------------- K3: transpose Wv -> g_WvT16 (n-major, fp16) ----------------
__global__ void k_t(const float* __restrict__ Wv) {
    __shared__ float ts[32][33];
    int x = threadIdx.x, y = threadIdx.y;           // 32 x 8
    int bx = blockIdx.x * 32, by = blockIdx.y * 32;
    #pragma unroll
    for (int j = 0; j < 32; j += 8) ts[y + j][x] = Wv[(by + y + j) * HIDDEN + bx + x];
    __syncthreads();
    #pragma unroll
    for (int j = 0; j < 32; j += 8)
        g_WvT16[(bx + y + j) * HIDDEN + by + x] = __float2half_rn(ts[x][y + j]);
}

// ---------------- K4: dots + segment max + drug->fp16 conversion -------------
__device__ __forceinline__ unsigned f_key(float f) {
    unsigned b = __float_as_uint(f);
    return (b & 0x80000000u) ? ~b : (b | 0x80000000u);
}
__device__ __forceinline__ float key_f(unsigned k) {
    return (k & 0x80000000u) ? __uint_as_float(k ^ 0x80000000u) : __uint_as_float(~k);
}
__device__ __forceinline__ unsigned pack2(float a, float b) {
    __half2 h = __float22half2_rn(make_float2(a, b));
    return *(unsigned*)&h;
}

__global__ void k_dots(const float* __restrict__ drug, const int* __restrict__ bidx) {
    int warp = threadIdx.x >> 5, lane = threadIdx.x & 31;
    int i0 = (blockIdx.x * 8 + warp) * 2;
    int b0 = bidx[i0], b1 = bidx[i0 + 1];
    const float4* d0 = (const float4*)(drug + (size_t)i0 * HIDDEN);
    const float4* d1 = (const float4*)(drug + (size_t)(i0 + 1) * HIDDEN);
    const float4* u0 = (const float4*)(g_U + (size_t)b0 * HIDDEN);
    const float4* u1 = (const float4*)(g_U + (size_t)b1 * HIDDEN);
    float4 x0 = d0[lane * 2], x1 = d0[lane * 2 + 1];
    float4 x2 = d1[lane * 2], x3 = d1[lane * 2 + 1];
    float4 y0 = u0[lane * 2], y1 = u0[lane * 2 + 1];
    float4 y2 = u1[lane * 2], y3 = u1[lane * 2 + 1];

    // emit fp16 copy (coalesced 16B per lane per atom)
    uint4 p0 = make_uint4(pack2(x0.x, x0.y), pack2(x0.z, x0.w),
                          pack2(x1.x, x1.y), pack2(x1.z, x1.w));
    uint4 p1 = make_uint4(pack2(x2.x, x2.y), pack2(x2.z, x2.w),
                          pack2(x3.x, x3.y), pack2(x3.z, x3.w));
    *(uint4*)(g_drug16 + (size_t)i0 * HIDDEN + lane * 8) = p0;
    *(uint4*)(g_drug16 + (size_t)(i0 + 1) * HIDDEN + lane * 8) = p1;

    float s0 = x0.x * y0.x + x0.y * y0.y + x0.z * y0.z + x0.w * y0.w
             + x1.x * y1.x + x1.y * y1.y + x1.z * y1.z + x1.w * y1.w;
    float s1 = x2.x * y2.x + x2.y * y2.y + x2.z * y2.z + x2.w * y2.w
             + x3.x * y3.x + x3.y * y3.y + x3.z * y3.z + x3.w * y3.w;
    #pragma unroll
    for (int off = 16; off > 0; off >>= 1) {
        s0 += __shfl_xor_sync(0xFFFFFFFFu, s0, off);
        s1 += __shfl_xor_sync(0xFFFFFFFFu, s1, off);
    }
    if (lane == 0) {
        float v0 = (s0 + g_c[b0]) * SCALE;
        float v1 = (s1 + g_c[b1]) * SCALE;
        g_e[i0]     = v0;
        g_e[i0 + 1] = v1;
        atomicMax(&g_segmax[b0], f_key(v0));
        atomicMax(&g_segmax[b1], f_key(v1));
    }
}

// ---------------- K5: e = exp(dots - m), segment sum ----------------
__global__ void k_exp(const int* __restrict__ bidx) {
    int i = blockIdx.x * blockDim.x + threadIdx.x;
    int b = bidx[i];
    float m = key_f(g_segmax[b]);
    float e = expf(g_e[i] - m);
    g_e[i] = e;
    atomicAdd(&g_segsum[b], e);
}

// ---------------- K6: persistent fp16-mma V-GEMM + attn*V + residual + LN ----
// grid=148 persistent, 512 threads, M=128 tiles. A: cp.async fp16, ping-pong
// across tiles. B: cp.async fp16 k=64 chunks, ping-pong within tile. All mma
// operands via ldmatrix; residual taken from the fp16 A tile in smem.

struct alignas(16) Sm {
    __half a2[2][128 * APITCH];        // 135,168 B
    __half b2[2][256 * BPITCH];        //  73,728 B
    float  attn[128];
    float  bvv[HIDDEN], gm[HIDDEN], bt[HIDDEN];
    float  rs[4][128], rq[4][128];
};

__device__ __forceinline__ void cp16(void* s, const void* g) {
    unsigned sa = (unsigned)__cvta_generic_to_shared(s);
    asm volatile("cp.async.cg.shared.global [%0], [%1], 16;" :: "r"(sa), "l"(g));
}
__device__ __forceinline__ void ldsm4(unsigned* r, unsigned addr) {
    asm volatile("ldmatrix.sync.aligned.m8n8.x4.shared.b16 {%0,%1,%2,%3}, [%4];"
        : "=r"(r[0]), "=r"(r[1]), "=r"(r[2]), "=r"(r[3]) : "r"(addr));
}
__device__ __forceinline__ void mma16(float* c, const unsigned* a, const unsigned* b) {
    asm volatile(
        "mma.sync.aligned.m16n8k16.row.col.f32.f16.f16.f32 "
        "{%0,%1,%2,%3},{%4,%5,%6,%7},{%8,%9},{%0,%1,%2,%3};"
        : "+f"(c[0]), "+f"(c[1]), "+f"(c[2]), "+f"(c[3])
        : "r"(a[0]), "r"(a[1]), "r"(a[2]), "r"(a[3]), "r"(b[0]), "r"(b[1]));
}

__device__ __forceinline__ void loadA(__half* dst, int tile, int t) {
    const __half* src = g_drug16 + (size_t)tile * 128 * HIDDEN;
    #pragma unroll
    for (int e = 0; e < 8; e++) {
        int idx = e * 512 + t;          // 4096 chunks of 8 halves
        int r = idx >> 5, j = idx & 31;
        cp16(dst + r * APITCH + j * 8, src + r * HIDDEN + j * 8);
    }
}
__device__ __forceinline__ void loadB(__half* dst, int c, int t) {
    const __half* src = g_WvT16 + c * 64;
    #pragma unroll
    for (int e = 0; e < 4; e++) {
        int idx = e * 512 + t;          // 2048 chunks of 8 halves
        int n = idx >> 3, j = idx & 7;
        cp16(dst + n * BPITCH + j * 8, src + n * HIDDEN + j * 8);
    }
}
#define COMMIT() asm volatile("cp.async.commit_group;")
#define WAITG(n) asm volatile("cp.async.wait_group %0;" :: "n"(n) : "memory")

__global__ void __launch_bounds__(512, 1) k_main(
    const float* __restrict__ bv, const float* __restrict__ gamma,
    const float* __restrict__ beta, const int* __restrict__ bidx,
    float* __restrict__ out, float* __restrict__ attn_out)
{
    extern __shared__ char smem_raw[];
    Sm& sm = *(Sm*)smem_raw;
    int t = threadIdx.x;
    int w = t >> 5, lane = t & 31;
    int g = lane >> 2, tig = lane & 3;
    int wm = w >> 2, wn = w & 3;       // 4x4 warps: 32 rows x 64 cols each

    if (t < 256) { sm.bvv[t] = bv[t]; sm.gm[t] = gamma[t]; sm.bt[t] = beta[t]; }

    // prologue: A(tile0) as its own group
    int tl = blockIdx.x;
    loadA(sm.a2[0], tl, t);
    COMMIT();                                   // group: A_cur

    unsigned aBase[2], bBase[2];
    aBase[0] = (unsigned)__cvta_generic_to_shared(sm.a2[0]);
    aBase[1] = (unsigned)__cvta_generic_to_shared(sm.a2[1]);
    bBase[0] = (unsigned)__cvta_generic_to_shared(sm.b2[0]);
    bBase[1] = (unsigned)__cvta_generic_to_shared(sm.b2[1]);
    unsigned aLaneOff = (unsigned)((wm * 32 + (lane & 15)) * APITCH * 2
                                   + ((lane >> 4) << 3) * 2);
    unsigned bLaneRow = (unsigned)((wn * 64 + ((lane >> 4) << 3) + (lane & 7)) * BPITCH * 2);
    unsigned bLaneK   = (unsigned)((((lane >> 3) & 1) << 3) * 2);

    int abuf = 0;
    for (; tl < NTILES; tl += NCTAS) {
        int rb = tl * 128;
        int nxt = tl + NCTAS;

        loadB(sm.b2[0], 0, t); COMMIT();        // B0
        loadB(sm.b2[1], 1, t); COMMIT();        // B1
        if (nxt < NTILES) loadA(sm.a2[abuf ^ 1], nxt, t);
        COMMIT();                               // A_next (possibly empty)

        if (t < 128) {
            int i = rb + t;
            int b = bidx[i];
            float a = g_e[i] / (g_segsum[b] + SM_EPS);
            sm.attn[t] = a;
            if (attn_out) attn_out[i] = a;
        }

        float acc[2][8][4];
        #pragma unroll
        for (int mt = 0; mt < 2; mt++)
            #pragma unroll
            for (int nt = 0; nt < 8; nt++)
                #pragma unroll
                for (int q = 0; q < 4; q++) acc[mt][nt][q] = 0.f;

        unsigned aLane = aBase[abuf] + aLaneOff;

        // chunk pipeline: pending after commits = {A_cur?, B0, B1, A_next}
        #pragma unroll
        for (int c = 0; c < 4; c++) {
            if (c == 0)      WAITG(2);          // A_cur + B0 done
            else if (c == 1) WAITG(2);          // B1 done (B2, A_next may pend)
            else if (c == 2) WAITG(1);          // B2 (+A_next) done
            else             WAITG(0);          // B3 done
            __syncthreads();

            #pragma unroll
            for (int k16 = 0; k16 < 4; k16++) {
                int kA = c * 64 + k16 * 16;
                unsigned a0[4], a1[4];
                ldsm4(a0, aLane + (unsigned)(kA * 2));
                ldsm4(a1, aLane + (unsigned)(16 * APITCH * 2 + kA * 2));
                #pragma unroll
                for (int p = 0; p < 4; p++) {
                    unsigned bq[4];
                    ldsm4(bq, bBase[c & 1] + bLaneRow + (unsigned)(p * 16 * BPITCH * 2)
                              + (unsigned)(k16 * 16 * 2) + bLaneK);
                    mma16(acc[0][2 * p],     a0, &bq[0]);
                    mma16(acc[1][2 * p],     a1, &bq[0]);
                    mma16(acc[0][2 * p + 1], a0, &bq[2]);
                    mma16(acc[1][2 * p + 1], a1, &bq[2]);
                }
            }
            __syncthreads();                    // chunk buffer free for reuse
            if (c < 2) { loadB(sm.b2[c & 1], c + 2, t); COMMIT(); }  // B2, B3
        }

        // epilogue: v = attn*(acc+bv) + residual(fp16 A smem) ; LN across wn
        const __half* aP = sm.a2[abuf];
        float rsum[2][2], rsq[2][2];
        #pragma unroll
        for (int mt = 0; mt < 2; mt++) { rsum[mt][0] = rsum[mt][1] = 0.f;
                                         rsq[mt][0] = rsq[mt][1] = 0.f; }
        #pragma unroll
        for (int mt = 0; mt < 2; mt++) {
            int r0 = wm * 32 + mt * 16 + g, r1 = r0 + 8;
            float a0 = sm.attn[r0], a1 = sm.attn[r1];
            #pragma unroll
            for (int nt = 0; nt < 8; nt++) {
                int c0 = wn * 64 + nt * 8 + 2 * tig;
                float2 q0 = __half22float2(*(const __half2*)&aP[r0 * APITCH + c0]);
                float2 q1 = __half22float2(*(const __half2*)&aP[r1 * APITCH + c0]);
                float bv0 = sm.bvv[c0], bv1 = sm.bvv[c0 + 1];
                float v0 = fmaf(a0, acc[0][nt][0] + bv0, q0.x);
                float v1 = fmaf(a0, acc[0][nt][1] + bv1, q0.y);
                float v2 = fmaf(a1, acc[0][nt][2] + bv0, q1.x);
                float v3 = fmaf(a1, acc[0][nt][3] + bv1, q1.y);
                acc[0][nt][0] = v0; acc[0][nt][1] = v1;
                acc[0][nt][2] = v2; acc[0][nt][3] = v3;
                rsum[0][0] += v0 + v1;  rsq[0][0] += v0 * v0 + v1 * v1;
                rsum[0][1] += v2 + v3;  rsq[0][1] += v2 * v2 + v3 * v3;

                int s0 = r0 + 16, s1 = r1 + 16;   // mt=1 rows handled below
                (void)s0; (void)s1;
            }
            // fold mt loop manually: shift results into [mt] slots
            if (mt == 0) {
                rsum[1][0] = rsum[0][0]; rsq[1][0] = rsq[0][0];
                rsum[1][1] = rsum[0][1]; rsq[1][1] = rsq[0][1];
                rsum[0][0] = rsum[0][1] = rsq[0][0] = rsq[0][1] = 0.f;
                // swap acc[0] (just finished = mt0) into acc[1] storage
                #pragma unroll
                for (int nt = 0; nt < 8; nt++)
                    #pragma unroll
                    for (int q = 0; q < 4; q++) {
                        float tmp = acc[1][nt][q];
                        acc[1][nt][q] = acc[0][nt][q];
                        acc[0][nt][q] = tmp;
                    }
            }
        }
        // after loop: acc[1]/rsum[1] hold mt=0 results, acc[0]/rsum[0] hold mt=1
        #pragma unroll
        for (int off = 1; off <= 2; off <<= 1) {
            #pragma unroll
            for (int mt = 0; mt < 2; mt++)
                #pragma unroll
                for (int h = 0; h < 2; h++) {
                    rsum[mt][h] += __shfl_xor_sync(0xFFFFFFFFu, rsum[mt][h], off);
                    rsq[mt][h]  += __shfl_xor_sync(0xFFFFFFFFu, rsq[mt][h], off);
                }
        }
        if (tig == 0) {
            #pragma unroll
            for (int mt = 0; mt < 2; mt++)
                #pragma unroll
                for (int h = 0; h < 2; h++) {
                    int row = wm * 32 + (1 - mt) * 16 + h * 8 + g;  // mt index swapped
                    sm.rs[wn][row] = rsum[mt][h];
                    sm.rq[wn][row] = rsq[mt][h];
                }
        }
        __syncthreads();

        #pragma unroll
        for (int mt = 0; mt < 2; mt++) {      // mt: 0 -> acc[1] rows +0; 1 -> acc[0] rows +16
            float* accp = (mt == 0) ? &acc[1][0][0] : &acc[0][0][0];
            #pragma unroll
            for (int h = 0; h < 2; h++) {
                int row = wm * 32 + mt * 16 + h * 8 + g;
                float ts = sm.rs[0][row] + sm.rs[1][row] + sm.rs[2][row] + sm.rs[3][row];
                float tq = sm.rq[0][row] + sm.rq[1][row] + sm.rq[2][row] + sm.rq[3][row];
                float mu = ts * (1.f / HIDDEN);
                float var = tq * (1.f / HIDDEN) - mu * mu;
                float rstd = rsqrtf(var + LN_EPS);
                #pragma unroll
                for (int nt = 0; nt < 8; nt++) {
                    int c0 = wn * 64 + nt * 8 + 2 * tig;
                    float v0 = accp[nt * 4 + h * 2 + 0];
                    float v1 = accp[nt * 4 + h * 2 + 1];
                    float y0 = fmaf((v0 - mu) * rstd, sm.gm[c0],     sm.bt[c0]);
                    float y1 = fmaf((v1 - mu) * rstd, sm.gm[c0 + 1], sm.bt[c0 + 1]);
                    *(float2*)&out[(size_t)(rb + row) * HIDDEN + c0] = make_float2(y0, y1);
                }
            }
        }
        __syncthreads();                      // A buf reuse fence
        abuf ^= 1;
    }
}

// ---------------- host ----------------
extern "C" void kernel_launch(void* const* d_in, const int* in_sizes, int n_in,
                              void* d_out, int out_size) {
    const float* drug  = (const float*)d_in[0];
    const float* prot  = (const float*)d_in[1];
    const int*   bidx  = (const int*)d_in[2];
    const float* Wq    = (const float*)d_in[3];
    const float* bq    = (const float*)d_in[4];
    const float* Wk    = (const float*)d_in[5];
    const float* bk    = (const float*)d_in[6];
    const float* Wv    = (const float*)d_in[7];
    const float* bv    = (const float*)d_in[8];
    const float* gamma = (const float*)d_in[9];
    const float* beta  = (const float*)d_in[10];

    float* out = (float*)d_out;
    float* attn_out = (out_size >= (int)((size_t)N_ATOMS * HIDDEN + N_ATOMS))
                        ? out + (size_t)N_ATOMS * HIDDEN : nullptr;

    cudaFuncSetAttribute(k_main, cudaFuncAttributeMaxDynamicSharedMemorySize,
                         (int)sizeof(Sm));

    k_pre <<<33, 256>>>(Wq, bq, Wk, bk);                 // launch 0
    k_u   <<<BATCH / 16, 256>>>(prot);                   // launch 1
    k_t   <<<dim3(8, 8), dim3(32, 8)>>>(Wv);             // launch 2
    k_dots<<<N_ATOMS / 16, 256>>>(drug, bidx);           // launch 3
    k_exp <<<N_ATOMS / 256, 256>>>(bidx);                // launch 4
    k_main<<<NCTAS, 512, sizeof(Sm)>>>(bv, gamma, beta, bidx, out, attn_out);  // launch 5 (ncu -s 5)
}